// round 2
// baseline (speedup 1.0000x reference)
#include <cuda_runtime.h>
#include <cuda_bf16.h>
#include <cstdint>

// ---------------------------------------------------------------------------
// DynamicLoRALinear on GB300 (sm_103 baseline PTX — NO tcgen05 available:
// the harness compiles via compute_103, so 'a'-features are rejected).
//   out = x @ W^T + b + SCALING * ((x @ A[slot]) @ B[slot])
//
// Strategy:
//   1) 3xBF16 split folded into K:  x' = [xh | xl | xh]  (K' = 12288)
//                                   w' = [wh | wh | wl]
//      -> one plain bf16 GEMM, fp32 accum, rel err ~4e-6.
//   2) mma.sync.m16n8k16 GEMM: CTA 128x128, 4 warps (warp tile 64x64),
//      3-stage cp.async pipeline, SW128 swizzled smem, ldmatrix loads.
//   3) fp32 SIMT kernels for lora_h = x@A and epilogue (bias + h@B).
// ---------------------------------------------------------------------------

#define DINLINE __device__ __forceinline__

static constexpr int BB    = 8;
static constexpr int TT    = 1024;
static constexpr int INF   = 4096;
static constexpr int OUTF  = 4096;
static constexpr int RR    = 16;
static constexpr int M_TOT = BB * TT;          // 8192
static constexpr int KPRIME = 3 * INF;         // 12288
static constexpr float SCALING_F = 2.0f;       // ALPHA/R

// ------------------------- scratch (device globals) ------------------------
__device__ __align__(128) __nv_bfloat16 g_xa[(size_t)M_TOT * KPRIME]; // [xh|xl|xh]
__device__ __align__(128) __nv_bfloat16 g_wb[(size_t)OUTF  * KPRIME]; // [wh|wh|wl]
__device__ __align__(128) float         g_h[M_TOT * RR];

// ------------------------------ PTX helpers --------------------------------
DINLINE uint32_t smem_u32(const void* p) {
    uint32_t a;
    asm("{ .reg .u64 t; cvta.to.shared.u64 t, %1; cvt.u32.u64 %0, t; }"
        : "=r"(a) : "l"(p));
    return a;
}

#define SW128(off) ((off) ^ (((off) >> 3) & 0x70))

#define CP_ASYNC16(dst, src) \
    asm volatile("cp.async.cg.shared.global [%0], [%1], 16;" :: "r"(dst), "l"(src) : "memory")
#define CP_COMMIT() asm volatile("cp.async.commit_group;" ::: "memory")
#define CP_WAIT_1() asm volatile("cp.async.wait_group 1;" ::: "memory")
#define CP_WAIT_0() asm volatile("cp.async.wait_group 0;" ::: "memory")

#define LDSM_X4(r0, r1, r2, r3, a) \
    asm volatile("ldmatrix.sync.aligned.m8n8.x4.shared.b16 {%0,%1,%2,%3}, [%4];" \
                 : "=r"(r0), "=r"(r1), "=r"(r2), "=r"(r3) : "r"(a))

DINLINE void mma_bf16(float* d, const uint32_t* a, uint32_t b0, uint32_t b1) {
    asm volatile(
        "mma.sync.aligned.m16n8k16.row.col.f32.bf16.bf16.f32 "
        "{%0,%1,%2,%3}, {%4,%5,%6,%7}, {%8,%9}, {%0,%1,%2,%3};"
        : "+f"(d[0]), "+f"(d[1]), "+f"(d[2]), "+f"(d[3])
        : "r"(a[0]), "r"(a[1]), "r"(a[2]), "r"(a[3]), "r"(b0), "r"(b1));
}

// ---------------------------------------------------------------------------
// K1: split fp32 -> concatenated bf16 hi/lo layout (rows of KPRIME)
//   x: hi at [k] and [2*INF + k], lo at [INF + k]
//   W: hi at [k] and [INF + k],   lo at [2*INF + k]
// ---------------------------------------------------------------------------
__global__ void __launch_bounds__(256)
k_split3(const float* __restrict__ in, __nv_bfloat16* __restrict__ out,
         int rows, int hi2_off, int lo_off) {
    const int stride = gridDim.x * blockDim.x;
    const int total = rows << 10;                 // rows * (INF/4)
    for (int i = blockIdx.x * blockDim.x + threadIdx.x; i < total; i += stride) {
        const int row = i >> 10, c4 = i & 1023;
        float4 v = ((const float4*)in)[i];
        __nv_bfloat16 h0 = __float2bfloat16(v.x);
        __nv_bfloat16 h1 = __float2bfloat16(v.y);
        __nv_bfloat16 h2 = __float2bfloat16(v.z);
        __nv_bfloat16 h3 = __float2bfloat16(v.w);
        __nv_bfloat162 hA = {h0, h1}, hB = {h2, h3};
        __nv_bfloat162 lA = {__float2bfloat16(v.x - __bfloat162float(h0)),
                             __float2bfloat16(v.y - __bfloat162float(h1))};
        __nv_bfloat162 lB = {__float2bfloat16(v.z - __bfloat162float(h2)),
                             __float2bfloat16(v.w - __bfloat162float(h3))};
        const size_t rb = (size_t)row * KPRIME;
        __nv_bfloat162* p;
        p = (__nv_bfloat162*)(out + rb + c4 * 4);            p[0] = hA; p[1] = hB;
        p = (__nv_bfloat162*)(out + rb + hi2_off + c4 * 4);  p[0] = hA; p[1] = hB;
        p = (__nv_bfloat162*)(out + rb + lo_off + c4 * 4);   p[0] = lA; p[1] = lB;
    }
}

// ---------------------------------------------------------------------------
// K2: lora_h[m][r] = sum_k x[m][k] * A[slot(m)][k][r]    (fp32)
// ---------------------------------------------------------------------------
__global__ void __launch_bounds__(256)
k_lorah(const float* __restrict__ x, const float* __restrict__ As,
        const int* __restrict__ map, float* __restrict__ h) {
    __shared__ float sA[256 * 16];
    __shared__ float sP[64 * 4 * 16];
    const int tid = threadIdx.x;
    const int m0  = blockIdx.x * 64;
    const int slot = map[m0 / TT];
    const float* Abase = As + (size_t)slot * INF * RR;
    const int tt = tid >> 2;
    const int q  = tid & 3;
    const float* xrow = x + (size_t)(m0 + tt) * INF;

    float acc[16];
#pragma unroll
    for (int r = 0; r < 16; ++r) acc[r] = 0.f;

    for (int c = 0; c < 16; ++c) {
        __syncthreads();
        const float4* src = (const float4*)(Abase + (size_t)c * 256 * 16);
#pragma unroll
        for (int ii = 0; ii < 4; ++ii)
            ((float4*)sA)[tid + ii * 256] = src[tid + ii * 256];
        __syncthreads();
#pragma unroll 4
        for (int jj = 0; jj < 16; ++jj) {
            int kloc = 16 * jj + 4 * q;
            float4 xv = *(const float4*)(xrow + c * 256 + kloc);
#pragma unroll
            for (int e = 0; e < 4; ++e) {
                float xs = (e == 0) ? xv.x : (e == 1) ? xv.y : (e == 2) ? xv.z : xv.w;
                const float* Ar = sA + (kloc + e) * 16;
#pragma unroll
                for (int r = 0; r < 16; ++r) acc[r] += xs * Ar[r];
            }
        }
    }
    __syncthreads();
#pragma unroll
    for (int r = 0; r < 16; ++r) sP[(tt * 4 + q) * 16 + r] = acc[r];
    __syncthreads();
    for (int o = tid; o < 64 * 16; o += 256) {
        int token = o >> 4, r = o & 15;
        float s = sP[(token * 4 + 0) * 16 + r] + sP[(token * 4 + 1) * 16 + r]
                + sP[(token * 4 + 2) * 16 + r] + sP[(token * 4 + 3) * 16 + r];
        h[(m0 + token) * 16 + r] = s;
    }
}

// ---------------------------------------------------------------------------
// K3: main GEMM  out[m][n] = sum_k' xa[m][k'] * wb[n][k']   (bf16 mma.sync)
// CTA 128x128, 4 warps (warp tile 64x64), K-chunk 64, 3-stage cp.async.
// ---------------------------------------------------------------------------
static constexpr int KC      = 64;
static constexpr int NCH     = KPRIME / KC;    // 192
static constexpr int TILE_B  = 128 * 128;      // 16KB (128 rows x 128B)
static constexpr int STAGE_B = 2 * TILE_B;     // A + B = 32KB
static constexpr int STAGES  = 3;
static constexpr uint32_t GEMM_SMEM = STAGES * STAGE_B + 1024;

__global__ void __launch_bounds__(128, 2)
k_gemm(const __nv_bfloat16* __restrict__ Abuf,
       const __nv_bfloat16* __restrict__ Bbuf,
       float* __restrict__ out) {
    extern __shared__ char smraw[];
    const uint32_t base = (smem_u32(smraw) + 1023u) & ~1023u;
    const int tid = threadIdx.x, wid = tid >> 5, lane = tid & 31;
    const int wm = wid >> 1, wn = wid & 1;
    const int m0 = blockIdx.y * 128, n0 = blockIdx.x * 128;
    const char* gA = (const char*)(Abuf + (size_t)m0 * KPRIME);
    const char* gB = (const char*)(Bbuf + (size_t)n0 * KPRIME);

    auto load_stage = [&](int s, int chunk) {
        const uint32_t sb = base + s * STAGE_B;
        const int kb = chunk * 128;              // 64 bf16 = 128 bytes
#pragma unroll
        for (int ii = 0; ii < 16; ++ii) {
            int u = tid + (ii << 7);             // 0..2047 16B units
            int t = u >> 10, e = u & 1023;
            int row = e >> 3, c16 = e & 7;
            const char* g = (t ? gB : gA) + (size_t)row * (KPRIME * 2) + kb + c16 * 16;
            CP_ASYNC16(sb + t * TILE_B + SW128((uint32_t)(row * 128 + c16 * 16)), g);
        }
        CP_COMMIT();
    };

    load_stage(0, 0);
    load_stage(1, 1);

    float acc[4][8][4];
#pragma unroll
    for (int a = 0; a < 4; ++a)
#pragma unroll
        for (int b = 0; b < 8; ++b)
#pragma unroll
            for (int c = 0; c < 4; ++c) acc[a][b][c] = 0.f;

    const int lrow = lane & 15;                  // ldmatrix row within 16
    const uint32_t lkh = (uint32_t)((lane >> 4) << 4);  // k-half byte offset

    for (int i = 0; i < NCH; ++i) {
        if (i == NCH - 1) { CP_WAIT_0(); } else { CP_WAIT_1(); }
        __syncthreads();
        if (i + 2 < NCH) load_stage((i + 2) % STAGES, i + 2);
        const uint32_t sA = base + (i % STAGES) * STAGE_B;
        const uint32_t sB = sA + TILE_B;
#pragma unroll
        for (int ks = 0; ks < 4; ++ks) {
            const uint32_t kc = (uint32_t)(ks * 32) + lkh;
            uint32_t ar[4][4], br[4][4];
#pragma unroll
            for (int t = 0; t < 4; ++t) {
                uint32_t a = sA + SW128((uint32_t)((wm * 64 + t * 16 + lrow) * 128) + kc);
                LDSM_X4(ar[t][0], ar[t][1], ar[t][2], ar[t][3], a);
            }
#pragma unroll
            for (int t = 0; t < 4; ++t) {
                uint32_t a = sB + SW128((uint32_t)((wn * 64 + t * 16 + lrow) * 128) + kc);
                LDSM_X4(br[t][0], br[t][1], br[t][2], br[t][3], a);
            }
#pragma unroll
            for (int tm = 0; tm < 4; ++tm)
#pragma unroll
                for (int tn = 0; tn < 8; ++tn)
                    mma_bf16(acc[tm][tn], ar[tm],
                             br[tn >> 1][tn & 1], br[tn >> 1][2 + (tn & 1)]);
        }
    }

    // epilogue: direct fp32 stores (bias + LoRA added by k_epilogue)
    const int erow = lane >> 2, ecol = (lane & 3) * 2;
#pragma unroll
    for (int tm = 0; tm < 4; ++tm) {
        const int rbase = m0 + wm * 64 + tm * 16 + erow;
#pragma unroll
        for (int tn = 0; tn < 8; ++tn) {
            float* p = out + (size_t)rbase * OUTF + n0 + wn * 64 + tn * 8 + ecol;
            *(float2*)p = make_float2(acc[tm][tn][0], acc[tm][tn][1]);
            *(float2*)(p + (size_t)8 * OUTF) = make_float2(acc[tm][tn][2], acc[tm][tn][3]);
        }
    }
}

// ---------------------------------------------------------------------------
// K4: out[m][n] += b[n] + SCALING * sum_r h[m][r] * B[slot(m)][r][n]
// ---------------------------------------------------------------------------
__global__ void __launch_bounds__(256)
k_epilogue(float* __restrict__ out, const float* __restrict__ bias,
           const float* __restrict__ Bs, const int* __restrict__ map,
           const float* __restrict__ h) {
    __shared__ float sB[16 * 512];
    __shared__ float sH[128 * 16];
    __shared__ float sbias[512];
    const int tid = threadIdx.x;
    const int m0 = blockIdx.y * 128;
    const int n0 = blockIdx.x * 512;
    const int slot = map[m0 / TT];
    const float* Bbase = Bs + (size_t)slot * RR * OUTF + n0;

#pragma unroll
    for (int ii = 0; ii < 8; ++ii) {
        int p = tid + ii * 256;
        int r = p >> 7, c4 = p & 127;
        ((float4*)sB)[p] = *(const float4*)(Bbase + (size_t)r * OUTF + c4 * 4);
    }
#pragma unroll
    for (int ii = 0; ii < 2; ++ii) {
        int p = tid + ii * 256;
        ((float4*)sH)[p] = *(const float4*)(h + m0 * 16 + p * 4);
    }
    if (tid < 128) ((float4*)sbias)[tid] = *(const float4*)(bias + n0 + tid * 4);
    __syncthreads();

    const int tok  = tid >> 1;
    const int half = tid & 1;
    float hreg[16];
#pragma unroll
    for (int r = 0; r < 16; ++r) hreg[r] = sH[tok * 16 + r];

    float* orow = out + (size_t)(m0 + tok) * OUTF + n0 + half * 256;
    const float* bcol = sbias + half * 256;
    const float* Bcol = sB + half * 256;

    for (int c = 0; c < 256; c += 4) {
        float4 a = make_float4(0.f, 0.f, 0.f, 0.f);
#pragma unroll
        for (int r = 0; r < 16; ++r) {
            float4 bv = *(const float4*)(Bcol + r * 512 + c);
            a.x += hreg[r] * bv.x; a.y += hreg[r] * bv.y;
            a.z += hreg[r] * bv.z; a.w += hreg[r] * bv.w;
        }
        float4 ov = *(float4*)(orow + c);
        float4 bb = *(const float4*)(bcol + c);
        ov.x += bb.x + SCALING_F * a.x;
        ov.y += bb.y + SCALING_F * a.y;
        ov.z += bb.z + SCALING_F * a.z;
        ov.w += bb.w + SCALING_F * a.w;
        *(float4*)(orow + c) = ov;
    }
}

// ---------------------------------------------------------------------------
extern "C" void kernel_launch(void* const* d_in, const int* in_sizes, int n_in,
                              void* d_out, int out_size) {
    const float* x    = (const float*)d_in[0];
    const int*   map  = (const int*)d_in[1];
    const float* W    = (const float*)d_in[2];
    const float* bias = (const float*)d_in[3];
    const float* As   = (const float*)d_in[4];
    const float* Bs   = (const float*)d_in[5];
    float* out = (float*)d_out;

    __nv_bfloat16 *xa, *wb;
    float* hbuf;
    cudaGetSymbolAddress((void**)&xa, g_xa);
    cudaGetSymbolAddress((void**)&wb, g_wb);
    cudaGetSymbolAddress((void**)&hbuf, g_h);

    cudaFuncSetAttribute(k_gemm, cudaFuncAttributeMaxDynamicSharedMemorySize,
                         (int)GEMM_SMEM);

    // x': hi at [k] and [2*INF+k], lo at [INF+k]
    k_split3<<<2048, 256>>>(x, xa, M_TOT, 2 * INF, INF);
    // w': hi at [k] and [INF+k],  lo at [2*INF+k]
    k_split3<<<1024, 256>>>(W, wb, OUTF, INF, 2 * INF);
    k_lorah<<<M_TOT / 64, 256>>>(x, As, map, hbuf);
    k_gemm<<<dim3(OUTF / 128, M_TOT / 128), 128, GEMM_SMEM>>>(xa, wb, out);
    k_epilogue<<<dim3(OUTF / 512, M_TOT / 128), 256>>>(out, bias, Bs, map, hbuf);
}

// round 3
// speedup vs baseline: 1.1410x; 1.1410x over previous
#include <cuda_runtime.h>
#include <cuda_bf16.h>
#include <cstdint>

// ---------------------------------------------------------------------------
// DynamicLoRALinear on GB300 (sm_103 baseline PTX; tcgen05 not available)
//   out = x @ W^T + b + SCALING * ((x @ A[slot]) @ B[slot])
//
//   1) 3xBF16 split, K folded: logical K' = 12288 with term order
//         [xh*wh | xl*wh | xh*wl]
//      but stored deduplicated as x'=[xh|xl], w'=[wh|wl] (8192-wide) with a
//      chunk remap in the loader.
//   2) mma.sync.m16n8k16 GEMM: CTA 128x128, 4 warps (64x64 warp tile),
//      3-stage cp.async pipeline interleaved into the MMA stream,
//      SW128 swizzle + ldmatrix. Fused epilogue adds bias + 2*h@B[slot].
//   3) fp32 SIMT kernel for lora_h = x@A.
// ---------------------------------------------------------------------------

#define DINLINE __device__ __forceinline__

static constexpr int BB    = 8;
static constexpr int TT    = 1024;
static constexpr int INF   = 4096;
static constexpr int OUTF  = 4096;
static constexpr int RR    = 16;
static constexpr int M_TOT = BB * TT;          // 8192
static constexpr int KW    = 2 * INF;          // physical row width 8192
static constexpr int NCH   = 192;              // logical K' chunks of 64
static constexpr float SCALING_F = 2.0f;       // ALPHA/R

// ------------------------- scratch (device globals) ------------------------
__device__ __align__(128) __nv_bfloat16 g_xa[(size_t)M_TOT * KW]; // [xh|xl]
__device__ __align__(128) __nv_bfloat16 g_wb[(size_t)OUTF  * KW]; // [wh|wl]
__device__ __align__(128) float         g_h[M_TOT * RR];

// ------------------------------ PTX helpers --------------------------------
DINLINE uint32_t smem_u32(const void* p) {
    uint32_t a;
    asm("{ .reg .u64 t; cvta.to.shared.u64 t, %1; cvt.u32.u64 %0, t; }"
        : "=r"(a) : "l"(p));
    return a;
}

#define SW128(off) ((off) ^ (((off) >> 3) & 0x70))

#define CP_ASYNC16(dst, src) \
    asm volatile("cp.async.cg.shared.global [%0], [%1], 16;" :: "r"(dst), "l"(src) : "memory")
#define CP_COMMIT() asm volatile("cp.async.commit_group;" ::: "memory")
#define CP_WAIT_1() asm volatile("cp.async.wait_group 1;" ::: "memory")
#define CP_WAIT_0() asm volatile("cp.async.wait_group 0;" ::: "memory")

#define LDSM_X4(r0, r1, r2, r3, a) \
    asm volatile("ldmatrix.sync.aligned.m8n8.x4.shared.b16 {%0,%1,%2,%3}, [%4];" \
                 : "=r"(r0), "=r"(r1), "=r"(r2), "=r"(r3) : "r"(a))

DINLINE void mma_bf16(float* d, const uint32_t* a, uint32_t b0, uint32_t b1) {
    asm volatile(
        "mma.sync.aligned.m16n8k16.row.col.f32.bf16.bf16.f32 "
        "{%0,%1,%2,%3}, {%4,%5,%6,%7}, {%8,%9}, {%0,%1,%2,%3};"
        : "+f"(d[0]), "+f"(d[1]), "+f"(d[2]), "+f"(d[3])
        : "r"(a[0]), "r"(a[1]), "r"(a[2]), "r"(a[3]), "r"(b0), "r"(b1));
}

// ---------------------------------------------------------------------------
// K1: split fp32 rows of INF -> bf16 rows of KW: hi at [k], lo at [INF+k]
// ---------------------------------------------------------------------------
__global__ void __launch_bounds__(256)
k_split(const float* __restrict__ in, __nv_bfloat16* __restrict__ out, int total4) {
    const int stride = gridDim.x * blockDim.x;
    for (int i = blockIdx.x * blockDim.x + threadIdx.x; i < total4; i += stride) {
        const int row = i >> 10, c4 = i & 1023;     // 1024 float4 per input row
        float4 v = ((const float4*)in)[i];
        __nv_bfloat16 h0 = __float2bfloat16(v.x);
        __nv_bfloat16 h1 = __float2bfloat16(v.y);
        __nv_bfloat16 h2 = __float2bfloat16(v.z);
        __nv_bfloat16 h3 = __float2bfloat16(v.w);
        __nv_bfloat162 hA = {h0, h1}, hB = {h2, h3};
        __nv_bfloat162 lA = {__float2bfloat16(v.x - __bfloat162float(h0)),
                             __float2bfloat16(v.y - __bfloat162float(h1))};
        __nv_bfloat162 lB = {__float2bfloat16(v.z - __bfloat162float(h2)),
                             __float2bfloat16(v.w - __bfloat162float(h3))};
        const size_t rb = (size_t)row * KW;
        __nv_bfloat162* p;
        p = (__nv_bfloat162*)(out + rb + c4 * 4);        p[0] = hA; p[1] = hB;
        p = (__nv_bfloat162*)(out + rb + INF + c4 * 4);  p[0] = lA; p[1] = lB;
    }
}

// ---------------------------------------------------------------------------
// K2: lora_h[m][r] = sum_k x[m][k] * A[slot(m)][k][r]    (fp32)
// ---------------------------------------------------------------------------
__global__ void __launch_bounds__(256)
k_lorah(const float* __restrict__ x, const float* __restrict__ As,
        const int* __restrict__ map, float* __restrict__ h) {
    __shared__ float sA[256 * 16];
    __shared__ float sP[64 * 4 * 16];
    const int tid = threadIdx.x;
    const int m0  = blockIdx.x * 64;
    const int slot = map[m0 / TT];
    const float* Abase = As + (size_t)slot * INF * RR;
    const int tt = tid >> 2;
    const int q  = tid & 3;
    const float* xrow = x + (size_t)(m0 + tt) * INF;

    float acc[16];
#pragma unroll
    for (int r = 0; r < 16; ++r) acc[r] = 0.f;

    for (int c = 0; c < 16; ++c) {
        __syncthreads();
        const float4* src = (const float4*)(Abase + (size_t)c * 256 * 16);
#pragma unroll
        for (int ii = 0; ii < 4; ++ii)
            ((float4*)sA)[tid + ii * 256] = src[tid + ii * 256];
        __syncthreads();
#pragma unroll 4
        for (int jj = 0; jj < 16; ++jj) {
            int kloc = 16 * jj + 4 * q;
            float4 xv = *(const float4*)(xrow + c * 256 + kloc);
#pragma unroll
            for (int e = 0; e < 4; ++e) {
                float xs = (e == 0) ? xv.x : (e == 1) ? xv.y : (e == 2) ? xv.z : xv.w;
                const float* Ar = sA + (kloc + e) * 16;
#pragma unroll
                for (int r = 0; r < 16; ++r) acc[r] += xs * Ar[r];
            }
        }
    }
    __syncthreads();
#pragma unroll
    for (int r = 0; r < 16; ++r) sP[(tt * 4 + q) * 16 + r] = acc[r];
    __syncthreads();
    for (int o = tid; o < 64 * 16; o += 256) {
        int token = o >> 4, r = o & 15;
        float s = sP[(token * 4 + 0) * 16 + r] + sP[(token * 4 + 1) * 16 + r]
                + sP[(token * 4 + 2) * 16 + r] + sP[(token * 4 + 3) * 16 + r];
        h[(m0 + token) * 16 + r] = s;
    }
}

// ---------------------------------------------------------------------------
// K3: GEMM + fused epilogue
// ---------------------------------------------------------------------------
static constexpr int TILE_B  = 128 * 128;      // 16KB (128 rows x 128B)
static constexpr int STAGE_B = 2 * TILE_B;     // A + B = 32KB
static constexpr int STAGES  = 3;
static constexpr uint32_t GEMM_SMEM = STAGES * STAGE_B + 1024;
static constexpr int ROWSTRIDE_B = KW * 2;     // 16384 bytes per gmem row

DINLINE int kmapA(int c) { return c < 128 ? c : c - 128; }  // [xh|xl|xh]
DINLINE int kmapB(int c) { return c < 64  ? c : c - 64;  }  // [wh|wh|wl]

__global__ void __launch_bounds__(128, 2)
k_gemm(const __nv_bfloat16* __restrict__ Abuf,
       const __nv_bfloat16* __restrict__ Bbuf,
       const float* __restrict__ bias,
       const float* __restrict__ Bs,
       const int* __restrict__ map,
       const float* __restrict__ h,
       float* __restrict__ out) {
    extern __shared__ char smraw[];
    const uint32_t raw  = smem_u32(smraw);
    const uint32_t base = (raw + 1023u) & ~1023u;
    char* p_base = smraw + (base - raw);
    const int tid = threadIdx.x, wid = tid >> 5, lane = tid & 31;
    const int wm = wid >> 1, wn = wid & 1;
    const int m0 = blockIdx.y * 128, n0 = blockIdx.x * 128;

    // per-thread load geometry (constant): 8 rows each for A and B tiles
    const char* gAt = (const char*)(Abuf + (size_t)m0 * KW)
                      + (size_t)(tid >> 3) * ROWSTRIDE_B + (tid & 7) * 16;
    const char* gBt = (const char*)(Bbuf + (size_t)n0 * KW)
                      + (size_t)(tid >> 3) * ROWSTRIDE_B + (tid & 7) * 16;
    uint32_t offs[8];
#pragma unroll
    for (int ii = 0; ii < 8; ++ii)
        offs[ii] = SW128((uint32_t)((((tid >> 3) + 16 * ii) * 128) + (tid & 7) * 16));

    auto load_full = [&](int s, int c) {
        const uint32_t sb = base + s * STAGE_B;
        const int kbA = kmapA(c) * 128, kbB = kmapB(c) * 128;
#pragma unroll
        for (int ii = 0; ii < 8; ++ii)
            CP_ASYNC16(sb + offs[ii], gAt + (size_t)ii * (16 * ROWSTRIDE_B) + kbA);
#pragma unroll
        for (int ii = 0; ii < 8; ++ii)
            CP_ASYNC16(sb + TILE_B + offs[ii], gBt + (size_t)ii * (16 * ROWSTRIDE_B) + kbB);
        CP_COMMIT();
    };

    load_full(0, 0);
    load_full(1, 1);

    float acc[4][8][4];
#pragma unroll
    for (int a = 0; a < 4; ++a)
#pragma unroll
        for (int b = 0; b < 8; ++b)
#pragma unroll
            for (int c = 0; c < 4; ++c) acc[a][b][c] = 0.f;

    const int lrow = lane & 15;
    const uint32_t lkh = (uint32_t)((lane >> 4) << 4);

    for (int i = 0; i < NCH; ++i) {
        if (i == NCH - 1) { CP_WAIT_0(); } else { CP_WAIT_1(); }
        __syncthreads();
        const bool doload = (i + 2 < NCH);
        const uint32_t sld = base + ((i + 2) % STAGES) * STAGE_B;
        const int kbA = kmapA(i + 2) * 128, kbB = kmapB(i + 2) * 128;
        const uint32_t sA = base + (i % STAGES) * STAGE_B;
        const uint32_t sB = sA + TILE_B;
#pragma unroll
        for (int ks = 0; ks < 4; ++ks) {
            if (doload) {   // interleave 4 of the 16 next-stage loads per ks
                const int i0 = 2 * ks, i1 = 2 * ks + 1;
                CP_ASYNC16(sld + offs[i0],
                           gAt + (size_t)i0 * (16 * ROWSTRIDE_B) + kbA);
                CP_ASYNC16(sld + offs[i1],
                           gAt + (size_t)i1 * (16 * ROWSTRIDE_B) + kbA);
                CP_ASYNC16(sld + TILE_B + offs[i0],
                           gBt + (size_t)i0 * (16 * ROWSTRIDE_B) + kbB);
                CP_ASYNC16(sld + TILE_B + offs[i1],
                           gBt + (size_t)i1 * (16 * ROWSTRIDE_B) + kbB);
            }
            const uint32_t kc = (uint32_t)(ks * 32) + lkh;
            uint32_t ar[4][4], br[4][4];
#pragma unroll
            for (int t = 0; t < 4; ++t) {
                uint32_t a = sA + SW128((uint32_t)((wm * 64 + t * 16 + lrow) * 128) + kc);
                LDSM_X4(ar[t][0], ar[t][1], ar[t][2], ar[t][3], a);
            }
#pragma unroll
            for (int t = 0; t < 4; ++t) {
                uint32_t a = sB + SW128((uint32_t)((wn * 64 + t * 16 + lrow) * 128) + kc);
                LDSM_X4(br[t][0], br[t][1], br[t][2], br[t][3], a);
            }
#pragma unroll
            for (int tm = 0; tm < 4; ++tm)
#pragma unroll
                for (int tn = 0; tn < 8; ++tn)
                    mma_bf16(acc[tm][tn], ar[tm],
                             br[tn >> 1][tn & 1], br[tn >> 1][2 + (tn & 1)]);
        }
        if (doload) CP_COMMIT();
    }

    // ---------------- fused epilogue: out = acc + bias + 2 * h @ B[slot] ----
    float* sH    = (float*)p_base;        // 128 x 16  (8KB)
    float* sBm   = sH + 2048;             // 16 x 128  (8KB)
    float* sbias = sBm + 2048;            // 128       (512B)
    const int slot = map[m0 >> 10];
    {
        const float4* hs = (const float4*)(h + (size_t)m0 * 16);
#pragma unroll
        for (int q = tid; q < 512; q += 128) ((float4*)sH)[q] = hs[q];
        const float* Bbase = Bs + (size_t)slot * RR * OUTF + n0;
#pragma unroll
        for (int q = tid; q < 512; q += 128) {
            int r = q >> 5, c4 = q & 31;
            ((float4*)sBm)[q] = *(const float4*)(Bbase + (size_t)r * OUTF + c4 * 4);
        }
        if (tid < 32) ((float4*)sbias)[tid] = ((const float4*)(bias + n0))[tid];
    }
    __syncthreads();

    const int erow = lane >> 2, ecol = (lane & 3) * 2;
#pragma unroll
    for (int tm = 0; tm < 4; ++tm) {
        const int r0 = wm * 64 + tm * 16 + erow;     // local rows r0, r0+8
        float h0[16], h1[16];
#pragma unroll
        for (int r = 0; r < 16; ++r) { h0[r] = sH[r0 * 16 + r]; h1[r] = sH[(r0 + 8) * 16 + r]; }
#pragma unroll
        for (int tn = 0; tn < 8; ++tn) {
            const int nl = wn * 64 + tn * 8 + ecol;
            float d00 = 0.f, d01 = 0.f, d10 = 0.f, d11 = 0.f;
#pragma unroll
            for (int r = 0; r < 16; ++r) {
                float B0 = sBm[r * 128 + nl], B1 = sBm[r * 128 + nl + 1];
                d00 += h0[r] * B0; d01 += h0[r] * B1;
                d10 += h1[r] * B0; d11 += h1[r] * B1;
            }
            const float b0 = sbias[nl], b1 = sbias[nl + 1];
            float* p = out + (size_t)(m0 + r0) * OUTF + n0 + nl;
            *(float2*)p = make_float2(acc[tm][tn][0] + b0 + SCALING_F * d00,
                                      acc[tm][tn][1] + b1 + SCALING_F * d01);
            *(float2*)(p + (size_t)8 * OUTF) =
                make_float2(acc[tm][tn][2] + b0 + SCALING_F * d10,
                            acc[tm][tn][3] + b1 + SCALING_F * d11);
        }
    }
}

// ---------------------------------------------------------------------------
extern "C" void kernel_launch(void* const* d_in, const int* in_sizes, int n_in,
                              void* d_out, int out_size) {
    const float* x    = (const float*)d_in[0];
    const int*   map  = (const int*)d_in[1];
    const float* W    = (const float*)d_in[2];
    const float* bias = (const float*)d_in[3];
    const float* As   = (const float*)d_in[4];
    const float* Bs   = (const float*)d_in[5];
    float* out = (float*)d_out;

    __nv_bfloat16 *xa, *wb;
    float* hbuf;
    cudaGetSymbolAddress((void**)&xa, g_xa);
    cudaGetSymbolAddress((void**)&wb, g_wb);
    cudaGetSymbolAddress((void**)&hbuf, g_h);

    cudaFuncSetAttribute(k_gemm, cudaFuncAttributeMaxDynamicSharedMemorySize,
                         (int)GEMM_SMEM);

    k_split<<<2048, 256>>>(x, xa, M_TOT * (INF / 4));
    k_split<<<1024, 256>>>(W, wb, OUTF * (INF / 4));
    k_lorah<<<M_TOT / 64, 256>>>(x, As, map, hbuf);
    k_gemm<<<dim3(OUTF / 128, M_TOT / 128), 128, GEMM_SMEM>>>(
        xa, wb, bias, Bs, map, hbuf, out);
}